// round 7
// baseline (speedup 1.0000x reference)
#include <cuda_runtime.h>
#include <cuda_bf16.h>
#include <math.h>

// ---------------------------------------------------------------------------
// GCN 2-layer: out = log_softmax( A relu( (A x) W1 + b1 ) W2 + b2 )
//   layer1: aggregate x at dim 128 (gather via CSR), then GEMM -> 256 (+bias,relu)
//   layer2: GEMM 256 -> 64, then gather-aggregate at dim 64 fused with bias+log_softmax
//
// CRITICAL FIX vs prior rounds: __device__ global buffers are NEVER passed as
// host-side kernel arguments (host code sees the HOST SHADOW of a __device__
// symbol; on GB300 ATS that silently reads host .bss zeros). The GEMM now
// selects its input/output buffers via template parameter and references the
// globals directly in device code.
// ---------------------------------------------------------------------------

#define N_NODES 50000
#define N_EDGES 800000
#define IN_DIM 128
#define HID_DIM 256
#define OUT_DIM 64
#define NB 49   // ceil(N_NODES / 1024)

__device__ int   g_count[N_NODES];          // in-degree (edges only)
__device__ int   g_off[N_NODES + 1];        // CSR row offsets
__device__ int   g_cur[N_NODES];            // placement cursors
__device__ int   g_bsum[NB];                // per-block sums for scan
__device__ int   g_esrc[N_EDGES];           // src node per CSR slot
__device__ float g_w[N_EDGES];              // edge norm per CSR slot
__device__ float g_dis[N_NODES];            // (deg incl. self-loop)^{-1/2}
__device__ float g_aggx[(size_t)N_NODES * IN_DIM];
__device__ float g_h1[(size_t)N_NODES * HID_DIM];
__device__ float g_t2[(size_t)N_NODES * OUT_DIM];

// ---------------- CSR build ----------------
__global__ void k_zero_count(int n) {
    int i = blockIdx.x * blockDim.x + threadIdx.x;
    if (i < n) g_count[i] = 0;
}

__global__ void k_hist(const int* __restrict__ dst, int e) {
    int i = blockIdx.x * blockDim.x + threadIdx.x;
    if (i < e) atomicAdd(&g_count[dst[i]], 1);
}

// per-1024-chunk sums
__global__ __launch_bounds__(1024) void k_chunk_sum(int n) {
    __shared__ int sh[1024];
    int i = blockIdx.x * 1024 + threadIdx.x;
    sh[threadIdx.x] = (i < n) ? g_count[i] : 0;
    __syncthreads();
    for (int o = 512; o > 0; o >>= 1) {
        if (threadIdx.x < o) sh[threadIdx.x] += sh[threadIdx.x + o];
        __syncthreads();
    }
    if (threadIdx.x == 0) g_bsum[blockIdx.x] = sh[0];
}

// exclusive scan of the 49 chunk sums (tiny, single thread)
__global__ void k_scan_bases() {
    if (threadIdx.x == 0) {
        int run = 0;
        for (int b = 0; b < NB; b++) { int v = g_bsum[b]; g_bsum[b] = run; run += v; }
    }
}

// per-chunk exclusive scan -> offsets, cursors, deg^{-1/2}
__global__ __launch_bounds__(1024) void k_write_off(int n) {
    __shared__ int sh[1024];
    int i = blockIdx.x * 1024 + threadIdx.x;
    int c = (i < n) ? g_count[i] : 0;
    sh[threadIdx.x] = c;
    __syncthreads();
    for (int o = 1; o < 1024; o <<= 1) {
        int t = 0;
        if (threadIdx.x >= o) t = sh[threadIdx.x - o];
        __syncthreads();
        sh[threadIdx.x] += t;
        __syncthreads();
    }
    if (i < n) {
        int incl = sh[threadIdx.x];
        int off = g_bsum[blockIdx.x] + incl - c;   // exclusive
        g_off[i] = off;
        g_cur[i] = off;
        g_dis[i] = rsqrtf((float)(c + 1));         // +1 self-loop
        if (i == n - 1) g_off[n] = g_bsum[blockIdx.x] + incl;
    }
}

__global__ void k_place(const int* __restrict__ src, const int* __restrict__ dst, int e) {
    int i = blockIdx.x * blockDim.x + threadIdx.x;
    if (i >= e) return;
    int s = src[i], d = dst[i];
    int pos = atomicAdd(&g_cur[d], 1);
    g_esrc[pos] = s;
    g_w[pos] = g_dis[s] * g_dis[d];
}

// ---------------- layer-1 aggregation: gather, warp per node, dim 128 ------
__global__ __launch_bounds__(256) void k_agg128(const float* __restrict__ x) {
    int gid = blockIdx.x * blockDim.x + threadIdx.x;
    int node = gid >> 5;
    int lane = gid & 31;
    if (node >= N_NODES) return;
    const float4* xv = reinterpret_cast<const float4*>(x);
    float dis = g_dis[node];
    float s2 = dis * dis;
    float4 acc = xv[(size_t)node * 32 + lane];     // self-loop
    acc.x *= s2; acc.y *= s2; acc.z *= s2; acc.w *= s2;
    int p1 = g_off[node + 1];
    for (int p = g_off[node]; p < p1; p++) {
        int s = g_esrc[p];
        float wt = g_w[p];
        float4 v = xv[(size_t)s * 32 + lane];
        acc.x = fmaf(wt, v.x, acc.x);
        acc.y = fmaf(wt, v.y, acc.y);
        acc.z = fmaf(wt, v.z, acc.z);
        acc.w = fmaf(wt, v.w, acc.w);
    }
    reinterpret_cast<float4*>(g_aggx)[(size_t)node * 32 + lane] = acc;
}

// ---------------- GEMM: C[M,N] = act(A[M,K] @ W[K,N] + bias) ----------------
// LAYER selects buffers via DEVICE-SIDE symbol references (never host-passed):
//   LAYER=1: A = g_aggx [N,128], C = g_h1 [N,256]
//   LAYER=2: A = g_h1  [N,256], C = g_t2 [N,64]
template <int LAYER, int N_COLS, int K_DIM, bool RELU, bool ADD_BIAS>
__global__ __launch_bounds__(256) void k_gemm(const float* __restrict__ W,
                                              const float* __restrict__ bias, int M) {
    const float* __restrict__ A = (LAYER == 1) ? g_aggx : g_h1;
    float* __restrict__ C       = (LAYER == 1) ? g_h1   : g_t2;

    constexpr int BM = 64, BN = 64, BK = 16;
    __shared__ float As[BK][BM + 4];
    __shared__ float Bs[BK][BN];
    int tid = threadIdx.x;
    int row0 = blockIdx.x * BM;
    int col0 = blockIdx.y * BN;
    int tx = tid & 15, ty = tid >> 4;

    float acc[4][4] = {};

    for (int k0 = 0; k0 < K_DIM; k0 += BK) {
        #pragma unroll
        for (int i = 0; i < 4; i++) {
            int idx = tid + i * 256;       // 64*16 = 1024 elems
            int m = idx >> 4, k = idx & 15;
            int gr = row0 + m;
            As[k][m] = (gr < M) ? A[(size_t)gr * K_DIM + k0 + k] : 0.0f;
        }
        #pragma unroll
        for (int i = 0; i < 4; i++) {
            int idx = tid + i * 256;       // 16*64 = 1024 elems
            int k = idx >> 6, n = idx & 63;
            Bs[k][n] = W[(size_t)(k0 + k) * N_COLS + col0 + n];
        }
        __syncthreads();
        #pragma unroll
        for (int k = 0; k < BK; k++) {
            float a[4], b[4];
            #pragma unroll
            for (int i = 0; i < 4; i++) a[i] = As[k][ty * 4 + i];
            #pragma unroll
            for (int j = 0; j < 4; j++) b[j] = Bs[k][tx * 4 + j];
            #pragma unroll
            for (int i = 0; i < 4; i++)
                #pragma unroll
                for (int j = 0; j < 4; j++)
                    acc[i][j] = fmaf(a[i], b[j], acc[i][j]);
        }
        __syncthreads();
    }

    #pragma unroll
    for (int i = 0; i < 4; i++) {
        int gr = row0 + ty * 4 + i;
        if (gr >= M) continue;
        #pragma unroll
        for (int j = 0; j < 4; j++) {
            int gc = col0 + tx * 4 + j;
            float v = acc[i][j];
            if (ADD_BIAS) v += bias[gc];
            if (RELU) v = fmaxf(v, 0.0f);
            C[(size_t)gr * N_COLS + gc] = v;
        }
    }
}

// ------- layer-2 aggregation (dim 64) fused with bias + log_softmax --------
// Conditional canaries: each term is EXACTLY 0.0 when the pipeline is healthy;
// if a stage silently read zeros, rel_err becomes a decodable bitmask.
__global__ __launch_bounds__(256) void k_agg64_softmax(float* __restrict__ out,
                                                       const float* __restrict__ b2,
                                                       const float* __restrict__ x,
                                                       const float* __restrict__ W1) {
    int gid = blockIdx.x * blockDim.x + threadIdx.x;
    int node = gid >> 5;
    int lane = gid & 31;
    if (node >= N_NODES) return;
    const float2* tv = reinterpret_cast<const float2*>(g_t2);
    float dis = g_dis[node];
    float s2 = dis * dis;
    float2 acc = tv[(size_t)node * 32 + lane];     // self-loop
    acc.x *= s2; acc.y *= s2;
    int p1 = g_off[node + 1];
    for (int p = g_off[node]; p < p1; p++) {
        int s = g_esrc[p];
        float wt = g_w[p];
        float2 v = tv[(size_t)s * 32 + lane];
        acc.x = fmaf(wt, v.x, acc.x);
        acc.y = fmaf(wt, v.y, acc.y);
    }

    // --- diagnostic canaries (0.0 contribution when all stages are live) ---
    float canary = 0.0f;
    if (x[5] == 0.0f && x[777] == 0.0f)                       canary += 0.64f;
    if (W1[3] == 0.0f && W1[1000] == 0.0f)                    canary += 0.32f;
    if (g_aggx[12345] == 0.0f && g_aggx[4000001] == 0.0f)     canary += 0.16f;
    if (g_h1[54321] == 0.0f && g_h1[9000001] == 0.0f)         canary += 0.08f;
    if (g_dis[7] == 0.0f)                                     canary += 0.04f;
    if (g_off[N_NODES] != N_EDGES)                            canary += 0.02f;
    // lane-alternating, row-mean-zero beacon survives log_softmax
    float2 bb = reinterpret_cast<const float2*>(b2)[lane];
    float vx = acc.x + bb.x + canary;
    float vy = acc.y + bb.y - canary;

    float m = fmaxf(vx, vy);
    #pragma unroll
    for (int o = 16; o > 0; o >>= 1) m = fmaxf(m, __shfl_xor_sync(0xFFFFFFFF, m, o));
    float s = expf(vx - m) + expf(vy - m);
    #pragma unroll
    for (int o = 16; o > 0; o >>= 1) s += __shfl_xor_sync(0xFFFFFFFF, s, o);
    float lse = m + logf(s);

    float2 r;
    r.x = vx - lse;
    r.y = vy - lse;
    reinterpret_cast<float2*>(out + (size_t)node * OUT_DIM)[lane] = r;
}

// ---------------------------------------------------------------------------
extern "C" void kernel_launch(void* const* d_in, const int* in_sizes, int n_in,
                              void* d_out, int out_size) {
    // Identify inputs by UNIQUE element count — robust to any harness ordering.
    const float* x  = nullptr;   // 50000*128 = 6400000
    const int*   ei = nullptr;   // 2*800000  = 1600000
    const float* W1 = nullptr;   // 128*256   = 32768
    const float* b1 = nullptr;   // 256
    const float* W2 = nullptr;   // 256*64    = 16384
    const float* b2 = nullptr;   // 64
    for (int i = 0; i < n_in; i++) {
        switch (in_sizes[i]) {
            case N_NODES * IN_DIM:   x  = (const float*)d_in[i]; break;
            case 2 * N_EDGES:        ei = (const int*)d_in[i];   break;
            case IN_DIM * HID_DIM:   W1 = (const float*)d_in[i]; break;
            case HID_DIM:            b1 = (const float*)d_in[i]; break;
            case HID_DIM * OUT_DIM:  W2 = (const float*)d_in[i]; break;
            case OUT_DIM:            b2 = (const float*)d_in[i]; break;
            default: break;
        }
    }
    float* out = (float*)d_out;

    const int N = N_NODES;
    const int E = N_EDGES;
    const int* src = ei;
    const int* dst = ei + E;

    const int T = 256;

    // CSR build + normalization (int atomics only)
    k_zero_count<<<(N + T - 1) / T, T>>>(N);
    k_hist<<<(E + T - 1) / T, T>>>(dst, E);
    k_chunk_sum<<<NB, 1024>>>(N);
    k_scan_bases<<<1, 32>>>();
    k_write_off<<<NB, 1024>>>(N);
    k_place<<<(E + T - 1) / T, T>>>(src, dst, E);

    // layer 1: gather-aggregate x (dim 128), then GEMM 128->256 with bias+relu
    k_agg128<<<(N * 32 + T - 1) / T, T>>>(x);
    {
        dim3 g((N + 63) / 64, HID_DIM / 64);
        k_gemm<1, HID_DIM, IN_DIM, true, true><<<g, 256>>>(W1, b1, N);
    }

    // layer 2: GEMM 256->64, then gather-aggregate (dim 64) + bias + log_softmax
    {
        dim3 g((N + 63) / 64, OUT_DIM / 64);
        k_gemm<2, OUT_DIM, HID_DIM, false, false><<<g, 256>>>(W2, nullptr, N);
    }
    k_agg64_softmax<<<(N * 32 + T - 1) / T, T>>>(out, b2, x, W1);
}

// round 10
// speedup vs baseline: 1.8212x; 1.8212x over previous
#include <cuda_runtime.h>
#include <cuda_bf16.h>
#include <math.h>
#include <stdint.h>

// ---------------------------------------------------------------------------
// GCN 2-layer: out = log_softmax( A relu( (A x) W1 + b1 ) W2 + b2 )
//   layer1: aggregate x at dim 128 (gather via CSR), then TF32 tensor GEMM -> 256
//   layer2: TF32 tensor GEMM 256 -> 64, then gather-aggregate + bias + log_softmax
//
// RULE (learned R0-R7): __device__ global buffers are NEVER passed as host-side
// kernel arguments (host sees the host shadow; GB300 ATS silently reads zeros).
// GEMM selects its buffers via template parameter, device-side.
// ---------------------------------------------------------------------------

#define N_NODES 50000
#define N_EDGES 800000
#define IN_DIM 128
#define HID_DIM 256
#define OUT_DIM 64
#define NB 49   // ceil(N_NODES / 1024)

__device__ int   g_count[N_NODES];
__device__ int   g_off[N_NODES + 1];
__device__ int   g_cur[N_NODES];
__device__ int   g_bsum[NB];
__device__ int   g_esrc[N_EDGES];
__device__ float g_w[N_EDGES];
__device__ float g_dis[N_NODES];
__device__ float g_aggx[(size_t)N_NODES * IN_DIM];
__device__ float g_h1[(size_t)N_NODES * HID_DIM];
__device__ float g_t2[(size_t)N_NODES * OUT_DIM];

// ---------------- CSR build ----------------
__global__ void k_zero_count(int n) {
    int i = blockIdx.x * blockDim.x + threadIdx.x;
    if (i < n) g_count[i] = 0;
}

__global__ void k_hist(const int* __restrict__ dst, int e) {
    int i = blockIdx.x * blockDim.x + threadIdx.x;
    if (i < e) atomicAdd(&g_count[dst[i]], 1);
}

__global__ __launch_bounds__(1024) void k_chunk_sum(int n) {
    __shared__ int sh[1024];
    int i = blockIdx.x * 1024 + threadIdx.x;
    sh[threadIdx.x] = (i < n) ? g_count[i] : 0;
    __syncthreads();
    for (int o = 512; o > 0; o >>= 1) {
        if (threadIdx.x < o) sh[threadIdx.x] += sh[threadIdx.x + o];
        __syncthreads();
    }
    if (threadIdx.x == 0) g_bsum[blockIdx.x] = sh[0];
}

// exclusive scan of the 49 chunk sums with one 64-thread block (was 5.4us serial)
__global__ void k_scan_bases() {
    __shared__ int ws[2];
    int t = threadIdx.x;
    int lane = t & 31, w = t >> 5;
    int v = (t < NB) ? g_bsum[t] : 0;
    int s = v;
    #pragma unroll
    for (int o = 1; o < 32; o <<= 1) {
        int u = __shfl_up_sync(0xFFFFFFFF, s, o);
        if (lane >= o) s += u;
    }
    if (lane == 31) ws[w] = s;
    __syncthreads();
    int base = (w == 1) ? ws[0] : 0;
    if (t < NB) g_bsum[t] = base + s - v;   // exclusive
}

__global__ __launch_bounds__(1024) void k_write_off(int n) {
    __shared__ int sh[1024];
    int i = blockIdx.x * 1024 + threadIdx.x;
    int c = (i < n) ? g_count[i] : 0;
    sh[threadIdx.x] = c;
    __syncthreads();
    for (int o = 1; o < 1024; o <<= 1) {
        int t = 0;
        if (threadIdx.x >= o) t = sh[threadIdx.x - o];
        __syncthreads();
        sh[threadIdx.x] += t;
        __syncthreads();
    }
    if (i < n) {
        int incl = sh[threadIdx.x];
        int off = g_bsum[blockIdx.x] + incl - c;
        g_off[i] = off;
        g_cur[i] = off;
        g_dis[i] = rsqrtf((float)(c + 1));
        if (i == n - 1) g_off[n] = g_bsum[blockIdx.x] + incl;
    }
}

__global__ void k_place(const int* __restrict__ src, const int* __restrict__ dst, int e) {
    int i = blockIdx.x * blockDim.x + threadIdx.x;
    if (i >= e) return;
    int s = src[i], d = dst[i];
    int pos = atomicAdd(&g_cur[d], 1);
    g_esrc[pos] = s;
    g_w[pos] = g_dis[s] * g_dis[d];
}

// ---------------- layer-1 aggregation: gather, warp per node, dim 128 ------
__global__ __launch_bounds__(256) void k_agg128(const float* __restrict__ x) {
    int gid = blockIdx.x * blockDim.x + threadIdx.x;
    int node = gid >> 5;
    int lane = gid & 31;
    if (node >= N_NODES) return;
    const float4* xv = reinterpret_cast<const float4*>(x);
    float dis = g_dis[node];
    float s2 = dis * dis;
    float4 acc = xv[(size_t)node * 32 + lane];     // self-loop
    acc.x *= s2; acc.y *= s2; acc.z *= s2; acc.w *= s2;
    int p1 = g_off[node + 1];
    for (int p = g_off[node]; p < p1; p++) {
        int s = g_esrc[p];
        float wt = g_w[p];
        float4 v = xv[(size_t)s * 32 + lane];
        acc.x = fmaf(wt, v.x, acc.x);
        acc.y = fmaf(wt, v.y, acc.y);
        acc.z = fmaf(wt, v.z, acc.z);
        acc.w = fmaf(wt, v.w, acc.w);
    }
    reinterpret_cast<float4*>(g_aggx)[(size_t)node * 32 + lane] = acc;
}

// ---------------- TF32 tensor-core GEMM ------------------------------------
// C[M,N_COLS] = act(A[M,K_DIM] @ W[K_DIM,N_COLS] + bias)
// Block tile: BM=128 x BN, BK=32. Warp tile 64x32 (4x4 m16n8k8 atoms).
// LAYER selects A/C buffers device-side: 1: g_aggx->g_h1, 2: g_h1->g_t2.

__device__ __forceinline__ uint32_t f2tf32(float f) {
    uint32_t u;
    asm("cvt.rna.tf32.f32 %0, %1;" : "=r"(u) : "f"(f));
    return u;
}

__device__ __forceinline__ void mma_tf32(float c[4], const uint32_t a[4], const uint32_t b[2]) {
    asm volatile(
        "mma.sync.aligned.m16n8k8.row.col.f32.tf32.tf32.f32 "
        "{%0,%1,%2,%3}, {%4,%5,%6,%7}, {%8,%9}, {%0,%1,%2,%3};"
        : "+f"(c[0]), "+f"(c[1]), "+f"(c[2]), "+f"(c[3])
        : "r"(a[0]), "r"(a[1]), "r"(a[2]), "r"(a[3]), "r"(b[0]), "r"(b[1]));
}

template <int LAYER, int N_COLS, int K_DIM, int BN, bool RELU, bool ADD_BIAS>
__global__ __launch_bounds__(32 * 2 * (BN / 32)) void k_gemm_tc(
        const float* __restrict__ W, const float* __restrict__ bias, int M) {
    const float* __restrict__ A = (LAYER == 1) ? g_aggx : g_h1;
    float* __restrict__ C       = (LAYER == 1) ? g_h1   : g_t2;

    constexpr int BM = 128, BK = 32;
    constexpr int WN_CNT = BN / 32;              // warps along N
    constexpr int THREADS = 32 * 2 * WN_CNT;     // 2 warps along M
    constexpr int ASTRIDE = 36;                  // 32 + 4 pad (conflict-free frags)
    constexpr int BSTRIDE = BN + 4;

    __shared__ uint32_t As[BM * ASTRIDE];
    __shared__ uint32_t Bs[BK * BSTRIDE];

    int tid = threadIdx.x;
    int warp = tid >> 5, lane = tid & 31;
    int g = lane >> 2, t = lane & 3;
    int wm = warp & 1;           // 0..1
    int wn = warp >> 1;          // 0..WN_CNT-1
    int row0 = blockIdx.x * BM;
    int col0 = blockIdx.y * BN;

    float c[4][4][4];            // [mt][nt][reg]
    #pragma unroll
    for (int i = 0; i < 4; i++)
        #pragma unroll
        for (int j = 0; j < 4; j++)
            #pragma unroll
            for (int r = 0; r < 4; r++) c[i][j][r] = 0.0f;

    for (int k0 = 0; k0 < K_DIM; k0 += BK) {
        // ---- load A tile (BM x BK) as tf32 ----
        constexpr int AF4 = (BM * BK / 4) / THREADS;
        #pragma unroll
        for (int i = 0; i < AF4; i++) {
            int f = tid + i * THREADS;
            int row = f >> 3;            // 8 float4 per row (BK=32)
            int q = f & 7;
            int gr = row0 + row;
            float4 v = make_float4(0.f, 0.f, 0.f, 0.f);
            if (gr < M) v = *reinterpret_cast<const float4*>(A + (size_t)gr * K_DIM + k0 + q * 4);
            uint32_t* p = &As[row * ASTRIDE + q * 4];
            p[0] = f2tf32(v.x); p[1] = f2tf32(v.y); p[2] = f2tf32(v.z); p[3] = f2tf32(v.w);
        }
        // ---- load B tile (BK x BN) as tf32 ----
        constexpr int BF4 = (BK * BN / 4) / THREADS;
        constexpr int QPR = BN / 4;      // float4 per row
        #pragma unroll
        for (int i = 0; i < BF4; i++) {
            int f = tid + i * THREADS;
            int kr = f / QPR;
            int q = f % QPR;
            float4 v = *reinterpret_cast<const float4*>(W + (size_t)(k0 + kr) * N_COLS + col0 + q * 4);
            uint32_t* p = &Bs[kr * BSTRIDE + q * 4];
            p[0] = f2tf32(v.x); p[1] = f2tf32(v.y); p[2] = f2tf32(v.z); p[3] = f2tf32(v.w);
        }
        __syncthreads();

        #pragma unroll
        for (int k8 = 0; k8 < BK / 8; k8++) {
            int kb = k8 * 8;
            uint32_t a[4][4], b[4][2];
            #pragma unroll
            for (int mt = 0; mt < 4; mt++) {
                int r = wm * 64 + mt * 16 + g;
                a[mt][0] = As[r * ASTRIDE + kb + t];
                a[mt][1] = As[(r + 8) * ASTRIDE + kb + t];
                a[mt][2] = As[r * ASTRIDE + kb + t + 4];
                a[mt][3] = As[(r + 8) * ASTRIDE + kb + t + 4];
            }
            #pragma unroll
            for (int nt = 0; nt < 4; nt++) {
                int cc = wn * 32 + nt * 8 + g;
                b[nt][0] = Bs[(kb + t) * BSTRIDE + cc];
                b[nt][1] = Bs[(kb + t + 4) * BSTRIDE + cc];
            }
            #pragma unroll
            for (int mt = 0; mt < 4; mt++)
                #pragma unroll
                for (int nt = 0; nt < 4; nt++)
                    mma_tf32(c[mt][nt], a[mt], b[nt]);
        }
        __syncthreads();
    }

    // ---- epilogue ----
    #pragma unroll
    for (int mt = 0; mt < 4; mt++) {
        int r0 = row0 + wm * 64 + mt * 16 + g;
        #pragma unroll
        for (int nt = 0; nt < 4; nt++) {
            int col = col0 + wn * 32 + nt * 8 + 2 * t;
            float bb0 = 0.f, bb1 = 0.f;
            if (ADD_BIAS) { bb0 = bias[col]; bb1 = bias[col + 1]; }
            if (r0 < M) {
                float v0 = c[mt][nt][0] + bb0;
                float v1 = c[mt][nt][1] + bb1;
                if (RELU) { v0 = fmaxf(v0, 0.f); v1 = fmaxf(v1, 0.f); }
                *reinterpret_cast<float2*>(C + (size_t)r0 * N_COLS + col) = make_float2(v0, v1);
            }
            if (r0 + 8 < M) {
                float v0 = c[mt][nt][2] + bb0;
                float v1 = c[mt][nt][3] + bb1;
                if (RELU) { v0 = fmaxf(v0, 0.f); v1 = fmaxf(v1, 0.f); }
                *reinterpret_cast<float2*>(C + (size_t)(r0 + 8) * N_COLS + col) = make_float2(v0, v1);
            }
        }
    }
}

// ------- layer-2 aggregation (dim 64) fused with bias + log_softmax --------
__global__ __launch_bounds__(256) void k_agg64_softmax(float* __restrict__ out,
                                                       const float* __restrict__ b2,
                                                       const float* __restrict__ x,
                                                       const float* __restrict__ W1) {
    int gid = blockIdx.x * blockDim.x + threadIdx.x;
    int node = gid >> 5;
    int lane = gid & 31;
    if (node >= N_NODES) return;
    const float2* tv = reinterpret_cast<const float2*>(g_t2);
    float dis = g_dis[node];
    float s2 = dis * dis;
    float2 acc = tv[(size_t)node * 32 + lane];     // self-loop
    acc.x *= s2; acc.y *= s2;
    int p1 = g_off[node + 1];
    for (int p = g_off[node]; p < p1; p++) {
        int s = g_esrc[p];
        float wt = g_w[p];
        float2 v = tv[(size_t)s * 32 + lane];
        acc.x = fmaf(wt, v.x, acc.x);
        acc.y = fmaf(wt, v.y, acc.y);
    }

    // --- diagnostic canaries (0.0 contribution when all stages are live) ---
    float canary = 0.0f;
    if (x[5] == 0.0f && x[777] == 0.0f)                       canary += 0.64f;
    if (W1[3] == 0.0f && W1[1000] == 0.0f)                    canary += 0.32f;
    if (g_aggx[12345] == 0.0f && g_aggx[4000001] == 0.0f)     canary += 0.16f;
    if (g_h1[54321] == 0.0f && g_h1[9000001] == 0.0f)         canary += 0.08f;
    if (g_dis[7] == 0.0f)                                     canary += 0.04f;
    if (g_off[N_NODES] != N_EDGES)                            canary += 0.02f;

    float2 bb = reinterpret_cast<const float2*>(b2)[lane];
    float vx = acc.x + bb.x + canary;
    float vy = acc.y + bb.y - canary;

    float m = fmaxf(vx, vy);
    #pragma unroll
    for (int o = 16; o > 0; o >>= 1) m = fmaxf(m, __shfl_xor_sync(0xFFFFFFFF, m, o));
    float s = expf(vx - m) + expf(vy - m);
    #pragma unroll
    for (int o = 16; o > 0; o >>= 1) s += __shfl_xor_sync(0xFFFFFFFF, s, o);
    float lse = m + logf(s);

    float2 r;
    r.x = vx - lse;
    r.y = vy - lse;
    reinterpret_cast<float2*>(out + (size_t)node * OUT_DIM)[lane] = r;
}

// ---------------------------------------------------------------------------
extern "C" void kernel_launch(void* const* d_in, const int* in_sizes, int n_in,
                              void* d_out, int out_size) {
    // Identify inputs by UNIQUE element count — robust to any harness ordering.
    const float* x  = nullptr;   // 6400000
    const int*   ei = nullptr;   // 1600000
    const float* W1 = nullptr;   // 32768
    const float* b1 = nullptr;   // 256
    const float* W2 = nullptr;   // 16384
    const float* b2 = nullptr;   // 64
    for (int i = 0; i < n_in; i++) {
        switch (in_sizes[i]) {
            case N_NODES * IN_DIM:   x  = (const float*)d_in[i]; break;
            case 2 * N_EDGES:        ei = (const int*)d_in[i];   break;
            case IN_DIM * HID_DIM:   W1 = (const float*)d_in[i]; break;
            case HID_DIM:            b1 = (const float*)d_in[i]; break;
            case HID_DIM * OUT_DIM:  W2 = (const float*)d_in[i]; break;
            case OUT_DIM:            b2 = (const float*)d_in[i]; break;
            default: break;
        }
    }
    float* out = (float*)d_out;

    const int N = N_NODES;
    const int E = N_EDGES;
    const int* src = ei;
    const int* dst = ei + E;

    const int T = 256;

    // CSR build + normalization (int atomics only)
    k_zero_count<<<(N + T - 1) / T, T>>>(N);
    k_hist<<<(E + T - 1) / T, T>>>(dst, E);
    k_chunk_sum<<<NB, 1024>>>(N);
    k_scan_bases<<<1, 64>>>();
    k_write_off<<<NB, 1024>>>(N);
    k_place<<<(E + T - 1) / T, T>>>(src, dst, E);

    // layer 1: gather-aggregate x (dim 128), then TF32 GEMM 128->256 (+bias+relu)
    k_agg128<<<(N * 32 + T - 1) / T, T>>>(x);
    {
        dim3 g((N + 127) / 128, HID_DIM / 128);   // (391, 2)
        k_gemm_tc<1, HID_DIM, IN_DIM, 128, true, true><<<g, 256>>>(W1, b1, N);
    }

    // layer 2: TF32 GEMM 256->64, then gather-aggregate + bias + log_softmax
    {
        dim3 g((N + 127) / 128, OUT_DIM / 64);    // (391, 1)
        k_gemm_tc<2, OUT_DIM, HID_DIM, 64, false, false><<<g, 128>>>(W2, nullptr, N);
    }
    k_agg64_softmax<<<(N * 32 + T - 1) / T, T>>>(out, b2, x, W1);
}

// round 11
// speedup vs baseline: 2.0045x; 1.1007x over previous
#include <cuda_runtime.h>
#include <cuda_bf16.h>
#include <math.h>
#include <stdint.h>

// ---------------------------------------------------------------------------
// GCN 2-layer: out = log_softmax( A relu( (A x) W1 + b1 ) W2 + b2 )
//   bf16 datapath end-to-end: x,W1,W2 converted once; gathers + GEMMs in bf16;
//   fp32 accumulation everywhere; fp32 output.
//   layer1: CSR gather-aggregate x (bf16, dim128) -> bf16 MMA GEMM -> 256 (+bias,relu)
//   layer2: bf16 MMA GEMM 256->64 -> CSR gather-aggregate + bias + log_softmax
//
// RULE (learned R0-R7): __device__ global buffers are NEVER passed as host-side
// kernel arguments (host sees the host shadow; GB300 ATS silently reads zeros).
// All internal buffers are referenced device-side (template-selected).
// ---------------------------------------------------------------------------

#define N_NODES 50000
#define N_EDGES 800000
#define IN_DIM 128
#define HID_DIM 256
#define OUT_DIM 64

__device__ int   g_count[N_NODES];
__device__ int   g_off[N_NODES + 1];
__device__ int   g_cur[N_NODES];
__device__ int   g_cursor;
__device__ int   g_esrc[N_EDGES];
__device__ float g_w[N_EDGES];
__device__ float g_dis[N_NODES];
__device__ __nv_bfloat16 g_xb[(size_t)N_NODES * IN_DIM];
__device__ __nv_bfloat16 g_w1b[(size_t)HID_DIM * IN_DIM];   // [n][k] transposed
__device__ __nv_bfloat16 g_w2b[(size_t)OUT_DIM * HID_DIM];  // [n][k] transposed
__device__ __nv_bfloat16 g_aggxb[(size_t)N_NODES * IN_DIM];
__device__ __nv_bfloat16 g_h1b[(size_t)N_NODES * HID_DIM];
__device__ __nv_bfloat16 g_t2b[(size_t)N_NODES * OUT_DIM];

// ---------------- prep: zero counters + cvt x,W1,W2 to bf16 ----------------
__global__ __launch_bounds__(256) void k_prep(const float* __restrict__ x,
                                              const float* __restrict__ W1,
                                              const float* __restrict__ W2) {
    int t = blockIdx.x * blockDim.x + threadIdx.x;
    // x -> bf16, 4 elems per thread (1.6M threads)
    if (t < (N_NODES * IN_DIM) / 4) {
        float4 v = reinterpret_cast<const float4*>(x)[t];
        __nv_bfloat162 p0 = __floats2bfloat162_rn(v.x, v.y);
        __nv_bfloat162 p1 = __floats2bfloat162_rn(v.z, v.w);
        uint2 u;
        u.x = *reinterpret_cast<uint32_t*>(&p0);
        u.y = *reinterpret_cast<uint32_t*>(&p1);
        reinterpret_cast<uint2*>(g_xb)[t] = u;
    }
    if (t < N_NODES) g_count[t] = 0;
    if (t < IN_DIM * HID_DIM) {        // W1[k][n] -> g_w1b[n][k]
        int k = t / HID_DIM, n = t % HID_DIM;
        g_w1b[(size_t)n * IN_DIM + k] = __float2bfloat16_rn(W1[t]);
    }
    if (t < HID_DIM * OUT_DIM) {       // W2[k][n] -> g_w2b[n][k]
        int k = t / OUT_DIM, n = t % OUT_DIM;
        g_w2b[(size_t)n * HID_DIM + k] = __float2bfloat16_rn(W2[t]);
    }
    if (t == 0) g_cursor = 0;
}

// ---------------- CSR build ----------------
__global__ void k_hist(const int* __restrict__ dst, int e) {
    int i = blockIdx.x * blockDim.x + threadIdx.x;
    if (i < e) atomicAdd(&g_count[dst[i]], 1);
}

// fused per-chunk scan + atomic base grab (segments need not be node-ordered:
// lengths come from g_count, so any disjoint contiguous assignment is valid)
__global__ __launch_bounds__(1024) void k_offsets(int n) {
    __shared__ int sh[1024];
    __shared__ int sbase;
    int i = blockIdx.x * 1024 + threadIdx.x;
    int c = (i < n) ? g_count[i] : 0;
    sh[threadIdx.x] = c;
    __syncthreads();
    for (int o = 1; o < 1024; o <<= 1) {
        int t = 0;
        if (threadIdx.x >= o) t = sh[threadIdx.x - o];
        __syncthreads();
        sh[threadIdx.x] += t;
        __syncthreads();
    }
    if (threadIdx.x == 1023) sbase = atomicAdd(&g_cursor, sh[1023]);
    __syncthreads();
    if (i < n) {
        int off = sbase + sh[threadIdx.x] - c;   // exclusive within chunk
        g_off[i] = off;
        g_cur[i] = off;
        g_dis[i] = rsqrtf((float)(c + 1));       // +1 self-loop
    }
}

__global__ void k_place(const int* __restrict__ src, const int* __restrict__ dst, int e) {
    int i = blockIdx.x * blockDim.x + threadIdx.x;
    if (i >= e) return;
    int s = src[i], d = dst[i];
    int pos = atomicAdd(&g_cur[d], 1);
    g_esrc[pos] = s;
    g_w[pos] = g_dis[s] * g_dis[d];
}

// ------- layer-1 aggregation: gather bf16, warp per node, dim 128 ----------
__global__ __launch_bounds__(256) void k_agg128() {
    int gid = blockIdx.x * blockDim.x + threadIdx.x;
    int node = gid >> 5;
    int lane = gid & 31;
    if (node >= N_NODES) return;
    const uint2* xv = reinterpret_cast<const uint2*>(g_xb);  // 32 uint2 per row
    float dis = g_dis[node];
    float s2 = dis * dis;
    uint2 u = xv[(size_t)node * 32 + lane];                  // self-loop
    float2 lo = __bfloat1622float2(*reinterpret_cast<__nv_bfloat162*>(&u.x));
    float2 hi = __bfloat1622float2(*reinterpret_cast<__nv_bfloat162*>(&u.y));
    float a0 = lo.x * s2, a1 = lo.y * s2, a2 = hi.x * s2, a3 = hi.y * s2;
    int p0 = g_off[node];
    int p1 = p0 + g_count[node];
    for (int p = p0; p < p1; p++) {
        int s = g_esrc[p];
        float wt = g_w[p];
        uint2 v = xv[(size_t)s * 32 + lane];
        float2 vl = __bfloat1622float2(*reinterpret_cast<__nv_bfloat162*>(&v.x));
        float2 vh = __bfloat1622float2(*reinterpret_cast<__nv_bfloat162*>(&v.y));
        a0 = fmaf(wt, vl.x, a0);
        a1 = fmaf(wt, vl.y, a1);
        a2 = fmaf(wt, vh.x, a2);
        a3 = fmaf(wt, vh.y, a3);
    }
    __nv_bfloat162 r0 = __floats2bfloat162_rn(a0, a1);
    __nv_bfloat162 r1 = __floats2bfloat162_rn(a2, a3);
    uint2 w;
    w.x = *reinterpret_cast<uint32_t*>(&r0);
    w.y = *reinterpret_cast<uint32_t*>(&r1);
    reinterpret_cast<uint2*>(g_aggxb)[(size_t)node * 32 + lane] = w;
}

// ---------------- bf16 tensor-core GEMM ------------------------------------
// C[M,N_COLS] = act(A[M,K_DIM] @ Wb^T + bias), A bf16 row-major, Wb bf16 [n][k].
// Block tile BM=128 x BN, BK=32. Warp tile 64x32 (4x4 m16n8k16 atoms).
// LAYER selects buffers device-side: 1: g_aggxb->g_h1b (W=g_w1b),
//                                    2: g_h1b ->g_t2b (W=g_w2b).

__device__ __forceinline__ void mma_bf16(float c[4], const uint32_t a[4], const uint32_t b[2]) {
    asm volatile(
        "mma.sync.aligned.m16n8k16.row.col.f32.bf16.bf16.f32 "
        "{%0,%1,%2,%3}, {%4,%5,%6,%7}, {%8,%9}, {%0,%1,%2,%3};"
        : "+f"(c[0]), "+f"(c[1]), "+f"(c[2]), "+f"(c[3])
        : "r"(a[0]), "r"(a[1]), "r"(a[2]), "r"(a[3]), "r"(b[0]), "r"(b[1]));
}

template <int LAYER, int N_COLS, int K_DIM, int BN, bool RELU, bool ADD_BIAS>
__global__ __launch_bounds__(64 * (BN / 32)) void k_gemm_bf16(
        const float* __restrict__ bias, int M) {
    const __nv_bfloat16* __restrict__ A  = (LAYER == 1) ? g_aggxb : g_h1b;
    const __nv_bfloat16* __restrict__ Wb = (LAYER == 1) ? g_w1b   : g_w2b;
    __nv_bfloat16* __restrict__ C        = (LAYER == 1) ? g_h1b   : g_t2b;

    constexpr int BM = 128, BK = 32;
    constexpr int THREADS = 64 * (BN / 32);
    constexpr int AS = 20;   // uint32 stride: 16 data + 4 pad (conflict-free for g,t)

    __shared__ uint32_t As32[BM * AS];
    __shared__ uint32_t Bs32[BN * AS];

    int tid = threadIdx.x;
    int warp = tid >> 5, lane = tid & 31;
    int g = lane >> 2, t = lane & 3;
    int wm = warp & 1;
    int wn = warp >> 1;
    int row0 = blockIdx.x * BM;
    int col0 = blockIdx.y * BN;

    float c[4][4][4];
    #pragma unroll
    for (int i = 0; i < 4; i++)
        #pragma unroll
        for (int j = 0; j < 4; j++)
            #pragma unroll
            for (int r = 0; r < 4; r++) c[i][j][r] = 0.0f;

    for (int k0 = 0; k0 < K_DIM; k0 += BK) {
        // A tile: BM x 32 bf16 = BM*4 uint4
        constexpr int ALOADS = (BM * 4) / THREADS;
        #pragma unroll
        for (int i = 0; i < ALOADS; i++) {
            int f = tid + i * THREADS;
            int row = f >> 2, q = f & 3;
            int gr = row0 + row;
            uint4 u = make_uint4(0, 0, 0, 0);
            if (gr < M) u = *reinterpret_cast<const uint4*>(A + (size_t)gr * K_DIM + k0 + q * 8);
            uint32_t* p = &As32[row * AS + q * 4];
            p[0] = u.x; p[1] = u.y; p[2] = u.z; p[3] = u.w;
        }
        // B tile: BN x 32 bf16 (Wb is [n][k])
        constexpr int BLOADS = (BN * 4) / THREADS;
        #pragma unroll
        for (int i = 0; i < BLOADS; i++) {
            int f = tid + i * THREADS;
            int row = f >> 2, q = f & 3;
            uint4 u = *reinterpret_cast<const uint4*>(Wb + (size_t)(col0 + row) * K_DIM + k0 + q * 8);
            uint32_t* p = &Bs32[row * AS + q * 4];
            p[0] = u.x; p[1] = u.y; p[2] = u.z; p[3] = u.w;
        }
        __syncthreads();

        #pragma unroll
        for (int ch = 0; ch < 2; ch++) {        // two k16 chunks in BK=32
            int kb2 = ch * 8;
            uint32_t a[4][4], b[4][2];
            #pragma unroll
            for (int mt = 0; mt < 4; mt++) {
                int r = wm * 64 + mt * 16 + g;
                a[mt][0] = As32[r * AS + kb2 + t];
                a[mt][1] = As32[(r + 8) * AS + kb2 + t];
                a[mt][2] = As32[r * AS + kb2 + 4 + t];
                a[mt][3] = As32[(r + 8) * AS + kb2 + 4 + t];
            }
            #pragma unroll
            for (int nt = 0; nt < 4; nt++) {
                int cc = wn * 32 + nt * 8 + g;
                b[nt][0] = Bs32[cc * AS + kb2 + t];
                b[nt][1] = Bs32[cc * AS + kb2 + 4 + t];
            }
            #pragma unroll
            for (int mt = 0; mt < 4; mt++)
                #pragma unroll
                for (int nt = 0; nt < 4; nt++)
                    mma_bf16(c[mt][nt], a[mt], b[nt]);
        }
        __syncthreads();
    }

    // ---- epilogue: bias + relu + bf16 store ----
    #pragma unroll
    for (int mt = 0; mt < 4; mt++) {
        int r0 = row0 + wm * 64 + mt * 16 + g;
        #pragma unroll
        for (int nt = 0; nt < 4; nt++) {
            int col = col0 + wn * 32 + nt * 8 + 2 * t;
            float bb0 = 0.f, bb1 = 0.f;
            if (ADD_BIAS) { bb0 = bias[col]; bb1 = bias[col + 1]; }
            if (r0 < M) {
                float v0 = c[mt][nt][0] + bb0;
                float v1 = c[mt][nt][1] + bb1;
                if (RELU) { v0 = fmaxf(v0, 0.f); v1 = fmaxf(v1, 0.f); }
                *reinterpret_cast<__nv_bfloat162*>(C + (size_t)r0 * N_COLS + col) =
                    __floats2bfloat162_rn(v0, v1);
            }
            if (r0 + 8 < M) {
                float v0 = c[mt][nt][2] + bb0;
                float v1 = c[mt][nt][3] + bb1;
                if (RELU) { v0 = fmaxf(v0, 0.f); v1 = fmaxf(v1, 0.f); }
                *reinterpret_cast<__nv_bfloat162*>(C + (size_t)(r0 + 8) * N_COLS + col) =
                    __floats2bfloat162_rn(v0, v1);
            }
        }
    }
}

// ------- layer-2 aggregation (bf16, dim 64) + bias + log_softmax -----------
__global__ __launch_bounds__(256) void k_agg64_softmax(float* __restrict__ out,
                                                       const float* __restrict__ b2,
                                                       const float* __restrict__ x,
                                                       const float* __restrict__ W1) {
    int gid = blockIdx.x * blockDim.x + threadIdx.x;
    int node = gid >> 5;
    int lane = gid & 31;
    if (node >= N_NODES) return;
    const __nv_bfloat162* tv = reinterpret_cast<const __nv_bfloat162*>(g_t2b);  // 32 per row
    float dis = g_dis[node];
    float s2 = dis * dis;
    float2 acc = __bfloat1622float2(tv[(size_t)node * 32 + lane]);  // self-loop
    acc.x *= s2; acc.y *= s2;
    int p0 = g_off[node];
    int p1 = p0 + g_count[node];
    for (int p = p0; p < p1; p++) {
        int s = g_esrc[p];
        float wt = g_w[p];
        float2 v = __bfloat1622float2(tv[(size_t)s * 32 + lane]);
        acc.x = fmaf(wt, v.x, acc.x);
        acc.y = fmaf(wt, v.y, acc.y);
    }

    // --- diagnostic canaries (0.0 contribution when all stages are live) ---
    float canary = 0.0f;
    if (x[5] == 0.0f && x[777] == 0.0f)                       canary += 0.64f;
    if (W1[3] == 0.0f && W1[1000] == 0.0f)                    canary += 0.32f;
    if (__bfloat162float(g_aggxb[12345]) == 0.0f &&
        __bfloat162float(g_aggxb[4000001]) == 0.0f)           canary += 0.16f;
    if (__bfloat162float(g_h1b[54321]) == 0.0f &&
        __bfloat162float(g_h1b[9000001]) == 0.0f)             canary += 0.08f;
    if (g_dis[7] == 0.0f)                                     canary += 0.04f;
    if (g_cursor != N_EDGES)                                  canary += 0.02f;

    float2 bb = reinterpret_cast<const float2*>(b2)[lane];
    float vx = acc.x + bb.x + canary;
    float vy = acc.y + bb.y - canary;

    float m = fmaxf(vx, vy);
    #pragma unroll
    for (int o = 16; o > 0; o >>= 1) m = fmaxf(m, __shfl_xor_sync(0xFFFFFFFF, m, o));
    float s = expf(vx - m) + expf(vy - m);
    #pragma unroll
    for (int o = 16; o > 0; o >>= 1) s += __shfl_xor_sync(0xFFFFFFFF, s, o);
    float lse = m + logf(s);

    float2 r;
    r.x = vx - lse;
    r.y = vy - lse;
    reinterpret_cast<float2*>(out + (size_t)node * OUT_DIM)[lane] = r;
}

// ---------------------------------------------------------------------------
extern "C" void kernel_launch(void* const* d_in, const int* in_sizes, int n_in,
                              void* d_out, int out_size) {
    // Identify inputs by UNIQUE element count — robust to any harness ordering.
    const float* x  = nullptr;   // 6400000
    const int*   ei = nullptr;   // 1600000
    const float* W1 = nullptr;   // 32768
    const float* b1 = nullptr;   // 256
    const float* W2 = nullptr;   // 16384
    const float* b2 = nullptr;   // 64
    for (int i = 0; i < n_in; i++) {
        switch (in_sizes[i]) {
            case N_NODES * IN_DIM:   x  = (const float*)d_in[i]; break;
            case 2 * N_EDGES:        ei = (const int*)d_in[i];   break;
            case IN_DIM * HID_DIM:   W1 = (const float*)d_in[i]; break;
            case HID_DIM:            b1 = (const float*)d_in[i]; break;
            case HID_DIM * OUT_DIM:  W2 = (const float*)d_in[i]; break;
            case OUT_DIM:            b2 = (const float*)d_in[i]; break;
            default: break;
        }
    }
    float* out = (float*)d_out;

    const int N = N_NODES;
    const int E = N_EDGES;
    const int* src = ei;
    const int* dst = ei + E;

    const int T = 256;

    // prep (zero counters + bf16 conversions) and CSR build
    k_prep<<<(N * IN_DIM / 4 + T - 1) / T, T>>>(x, W1, W2);
    k_hist<<<(E + T - 1) / T, T>>>(dst, E);
    k_offsets<<<(N + 1023) / 1024, 1024>>>(N);
    k_place<<<(E + T - 1) / T, T>>>(src, dst, E);

    // layer 1: bf16 gather-aggregate (dim 128), bf16 GEMM 128->256 (+bias+relu)
    k_agg128<<<(N * 32 + T - 1) / T, T>>>();
    {
        dim3 g((N + 127) / 128, HID_DIM / 128);   // (391, 2)
        k_gemm_bf16<1, HID_DIM, IN_DIM, 128, true, true><<<g, 256>>>(b1, N);
    }

    // layer 2: bf16 GEMM 256->64, then bf16 gather-aggregate + bias + log_softmax
    {
        dim3 g((N + 127) / 128, 1);               // (391, 1)
        k_gemm_bf16<2, OUT_DIM, HID_DIM, 64, false, false><<<g, 128>>>(nullptr, N);
    }
    k_agg64_softmax<<<(N * 32 + T - 1) / T, T>>>(out, b2, x, W1);
}